// round 13
// baseline (speedup 1.0000x reference)
#include <cuda_runtime.h>
#include <math.h>

#define NB      16          // batch
#define MROWS   8192        // nvar * L
#define EDIM    768
#define QDIM    384
#define LSEQ    512
#define HDIM    1536
#define CHUNKS  128
#define RPC     (MROWS/CHUNKS)   // 64 rows per CTA
#define RPW     (RPC/8)          // 8 rows per warp
#define PSL     (EDIM/8)         // 96: e-slice for kC1b
#define KSL     16               // k-slice for kD
#define NKD     (HDIM/KSL)       // 96 slices
#define JG      (QDIM/KSL)       // 24 j-groups in kD phase 1

// ---- scratch (device globals; no allocs allowed) ----
__device__ float g_part[NB*CHUNKS*EDIM];// partial weighted pools (6.3 MB)
__device__ float g_wsum[NB*CHUNKS];
__device__ float g_pvp[NB*8*QDIM];      // partial pooled_v (k-split, 8 slices)
__device__ float g_h[NB*QDIM];          // LN output
__device__ float g_pv[NB*QDIM];         // pooled_v
__device__ float g_op[NKD*NB*QDIM];     // partial out (96 k-slices, 2.25 MB)

// --------------------------------------------------------- f32x2 packed math
typedef unsigned long long u64;

__device__ __forceinline__ void ffma2(u64 &d, u64 a, u64 b, u64 c) {
    asm("fma.rn.f32x2 %0, %1, %2, %3;" : "=l"(d) : "l"(a), "l"(b), "l"(c));
}
__device__ __forceinline__ float f32x2_sum(u64 v) {
    float lo, hi;
    asm("mov.b64 {%0, %1}, %2;" : "=f"(lo), "=f"(hi) : "l"(v));
    return lo + hi;
}
__device__ __forceinline__ u64 pack2(float lo, float hi) {
    u64 r;
    asm("mov.b64 %0, {%1, %2};" : "=l"(r) : "f"(lo), "f"(hi));
    return r;
}

// ---------------------------------------------------------------- reductions
__device__ __forceinline__ float blockReduce384(float v, float* s_red, int tid) {
    s_red[tid] = v; __syncthreads();
    if (tid < 128) s_red[tid] += s_red[tid + 128] + s_red[tid + 256];
    __syncthreads();
    #pragma unroll
    for (int o = 64; o > 0; o >>= 1) {
        if (tid < o) s_red[tid] += s_red[tid + o];
        __syncthreads();
    }
    float r = s_red[0]; __syncthreads();
    return r;
}

__device__ __forceinline__ float warpSum(float v) {
    #pragma unroll
    for (int o = 16; o > 0; o >>= 1) v += __shfl_xor_sync(0xffffffffu, v, o);
    return v;
}

// --------------------- kernel B: fused x-stream (FFMA2 packed) ---------------
// retrieval logit = 0.5*imp + 0.2*rec  (relevance is constant to ~2e-5 and
// cancels in the softmax; the whole query/Wk path is dead)
__global__ __launch_bounds__(256, 3)
void kB(const float* __restrict__ x, const float* __restrict__ Wcd,
        const float* __restrict__ bcd)
{
    __shared__ float s_c0[EDIM], s_c1[EDIM];
    __shared__ float s_rec[LSEQ];
    __shared__ float s_part[8][EDIM];
    __shared__ float s_ws[8];

    const int n = blockIdx.y, chunk = blockIdx.x;
    const int tid = threadIdx.x, lane = tid & 31, warp = tid >> 5;

    for (int e = tid; e < EDIM; e += 256) {
        s_c0[e] = Wcd[2*e];
        s_c1[e] = Wcd[2*e + 1];
    }
    for (int p = tid; p < LSEQ; p += 256)
        s_rec[p] = 0.2f * __expf(-0.00300450902029873f * (float)(511 - p));
    __syncthreads();

    const float b0 = bcd[0], b1v = bcd[1];

    const ulonglong2* c02 = reinterpret_cast<const ulonglong2*>(s_c0);
    const ulonglong2* c12 = reinterpret_cast<const ulonglong2*>(s_c1);

    u64 acc2[12];
    #pragma unroll
    for (int i = 0; i < 12; i++) acc2[i] = 0ull;
    float wsum = 0.f;

    const int row0 = chunk*RPC + warp*RPW;
    const ulonglong2* xb = reinterpret_cast<const ulonglong2*>(x)
                         + (size_t)n * MROWS * (EDIM/4) + lane;

    for (int r = 0; r < RPW; r += 2) {
        const int m = row0 + r;
        const ulonglong2* xra = xb + (size_t)m * (EDIM/4);
        const ulonglong2* xrb = xra + (EDIM/4);
        ulonglong2 va2[6], vb2[6];
        #pragma unroll
        for (int i = 0; i < 6; i++) va2[i] = xra[32*i];
        #pragma unroll
        for (int i = 0; i < 6; i++) vb2[i] = xrb[32*i];

        u64 d0a2 = 0, d1a2 = 0, d0b2 = 0, d1b2 = 0;
        #pragma unroll
        for (int i = 0; i < 6; i++) {
            const int idx = lane + 32*i;
            ulonglong2 w0 = c02[idx];       // one LDS.128 for both rows
            ffma2(d0a2, va2[i].x, w0.x, d0a2);
            ffma2(d0a2, va2[i].y, w0.y, d0a2);
            ffma2(d0b2, vb2[i].x, w0.x, d0b2);
            ffma2(d0b2, vb2[i].y, w0.y, d0b2);
            ulonglong2 w1 = c12[idx];
            ffma2(d1a2, va2[i].x, w1.x, d1a2);
            ffma2(d1a2, va2[i].y, w1.y, d1a2);
            ffma2(d1b2, vb2[i].x, w1.x, d1b2);
            ffma2(d1b2, vb2[i].y, w1.y, d1b2);
        }
        float d0a = f32x2_sum(d0a2), d1a = f32x2_sum(d1a2);
        float d0b = f32x2_sum(d0b2), d1b = f32x2_sum(d1b2);

        #pragma unroll
        for (int o = 16; o > 0; o >>= 1) {
            d0a += __shfl_xor_sync(0xffffffffu, d0a, o);
            d0b += __shfl_xor_sync(0xffffffffu, d0b, o);
            d1a += __shfl_xor_sync(0xffffffffu, d1a, o);
            d1b += __shfl_xor_sync(0xffffffffu, d1b, o);
        }

        // importance: imp = 1/(1+(A1/A0)^2), A = 1+e^z, z = -(cd + b)
        float A0a = 1.f + __expf(-(d0a + b0));
        float A1a = 1.f + __expf(-(d1a + b1v));
        float A0b = 1.f + __expf(-(d0b + b0));
        float A1b = 1.f + __expf(-(d1b + b1v));
        float ra  = __fdividef(A1a, A0a);
        float rb  = __fdividef(A1b, A0b);
        float impa = __fdividef(1.f, fmaf(ra, ra, 1.f));
        float impb = __fdividef(1.f, fmaf(rb, rb, 1.f));

        float reca = s_rec[ m      & (LSEQ-1)];
        float recb = s_rec[(m + 1) & (LSEQ-1)];

        float wA = __expf(0.5f*impa + reca);
        float wB = __expf(0.5f*impb + recb);
        wsum += wA + wB;

        u64 wA2 = pack2(wA, wA), wB2 = pack2(wB, wB);
        #pragma unroll
        for (int i = 0; i < 6; i++) {
            ffma2(acc2[2*i],   va2[i].x, wA2, acc2[2*i]);
            ffma2(acc2[2*i],   vb2[i].x, wB2, acc2[2*i]);
            ffma2(acc2[2*i+1], va2[i].y, wA2, acc2[2*i+1]);
            ffma2(acc2[2*i+1], vb2[i].y, wB2, acc2[2*i+1]);
        }
    }

    // warp partials -> smem, fixed-order CTA reduce
    ulonglong2* sp2 = reinterpret_cast<ulonglong2*>(s_part[warp]);
    #pragma unroll
    for (int i = 0; i < 6; i++)
        sp2[lane + 32*i] = make_ulonglong2(acc2[2*i], acc2[2*i+1]);
    if (lane == 0) s_ws[warp] = wsum;
    __syncthreads();

    float* gp = g_part + (size_t)(n*CHUNKS + chunk)*EDIM;
    for (int e = tid; e < EDIM; e += 256) {
        float s = 0.f;
        #pragma unroll
        for (int wi = 0; wi < 8; wi++) s += s_part[wi][e];
        gp[e] = s;
    }
    if (tid == 0) {
        float s = 0.f;
        #pragma unroll
        for (int wi = 0; wi < 8; wi++) s += s_ws[wi];
        g_wsum[n*CHUNKS + chunk] = s;
    }
}

// ----------- kC1b: reduce partial pools (own e-slice) + partial Wv matvec
//             grid (8, NB), 384 threads; 4 threads/element over 128 chunks
__global__ __launch_bounds__(QDIM)
void kC1b(const float* __restrict__ Wv)
{
    __shared__ float s_q[4][PSL];
    __shared__ float s_px[PSL];
    const int p = blockIdx.x, n = blockIdx.y, tid = threadIdx.x;
    const int ebase = p*PSL;
    const int el = tid % PSL, grp = tid / PSL;    // 4 threads per element

    {
        const float* pp = g_part + (size_t)n*CHUNKS*EDIM
                        + (size_t)(grp*(CHUNKS/4))*EDIM + ebase + el;
        float v[CHUNKS/4];                        // 32 loads in flight
        #pragma unroll
        for (int c = 0; c < CHUNKS/4; c++) v[c] = pp[(size_t)c*EDIM];
        float s = 0.f;
        #pragma unroll
        for (int c = 0; c < CHUNKS/4; c++) s += v[c];
        s_q[grp][el] = s;
    }
    __syncthreads();
    if (tid < PSL)
        s_px[tid] = (s_q[0][tid] + s_q[1][tid]) + (s_q[2][tid] + s_q[3][tid]);
    __syncthreads();

    // Wv matvec: 3 blocks of 32 register-prefetched weight loads
    float s = 0.f;
    const float* wv = Wv + (size_t)ebase*QDIM + tid;
    #pragma unroll
    for (int blk = 0; blk < 3; blk++) {
        float w[32];
        #pragma unroll
        for (int i = 0; i < 32; i++) w[i] = wv[(size_t)(blk*32 + i)*QDIM];
        #pragma unroll
        for (int i = 0; i < 32; i++) s += s_px[blk*32 + i]*w[i];
    }
    g_pvp[(n*8 + p)*QDIM + tid] = s;
}

// ----------- kC1c: wsum, combine partials, + bv, LayerNorm  (grid NB, 384)
__global__ __launch_bounds__(QDIM)
void kC1c(const float* __restrict__ bv, const float* __restrict__ lng,
          const float* __restrict__ lnb)
{
    __shared__ float s_red[QDIM];
    __shared__ float s_inv;
    const int n = blockIdx.x, tid = threadIdx.x;

    if (tid < 32) {
        float s = 0.f;
        #pragma unroll
        for (int q = 0; q < CHUNKS/32; q++) s += g_wsum[n*CHUNKS + tid + 32*q];
        s = warpSum(s);
        if (tid == 0) s_inv = 1.f/s;
    }
    __syncthreads();
    const float inv = s_inv;

    float s = 0.f;
    #pragma unroll
    for (int p = 0; p < 8; p++) s += g_pvp[(n*8 + p)*QDIM + tid];
    s = s*inv + bv[tid];

    float mean = blockReduce384(s, s_red, tid) * (1.f/(float)QDIM);
    float d    = s - mean;
    float var  = blockReduce384(d*d, s_red, tid) * (1.f/(float)QDIM);
    g_h[n*QDIM + tid]  = lng[tid]*d*rsqrtf(var + 1e-6f) + lnb[tid];
    g_pv[n*QDIM + tid] = s;
}

// ------------- kD: batched FFN. grid NKD=96, 384 thr, k-slice of 16.
// Register-prefetched weights + FFMA2/LDS.64 packed inner products.
__global__ __launch_bounds__(QDIM)
void kD(const float* __restrict__ W1, const float* __restrict__ b1,
        const float* __restrict__ Wmu)
{
    __shared__ float s_h[NB][QDIM];      // 24 KB
    __shared__ float s_acc[JG][NB*KSL];  // 24*256*4 = 24 KB
    __shared__ float s_h1[NB][KSL];      // 1 KB
    const int p = blockIdx.x, tid = threadIdx.x;
    const int kl = tid % KSL, g = tid / KSL;   // 16 k-lanes x 24 j-groups
    const int k = p*KSL + kl;

    // cooperative h load, float4 (4 iters)
    {
        const float4* gh4 = reinterpret_cast<const float4*>(g_h);
        float4* sh4 = reinterpret_cast<float4*>(&s_h[0][0]);
        #pragma unroll
        for (int q = 0; q < NB*QDIM/4/QDIM; q++)
            sh4[tid + q*QDIM] = gh4[tid + q*QDIM];
    }
    __syncthreads();

    // phase 1: prefetch 16 W1 weights -> 8 packed pairs, then FFMA2
    {
        const float* w1p = W1 + (size_t)(g*KSL)*HDIM + k;
        float w[KSL];
        #pragma unroll
        for (int j = 0; j < KSL; j++) w[j] = w1p[(size_t)j*HDIM];
        u64 w2[KSL/2];
        #pragma unroll
        for (int j2 = 0; j2 < KSL/2; j2++) w2[j2] = pack2(w[2*j2], w[2*j2+1]);

        u64 acc2[NB];
        #pragma unroll
        for (int n = 0; n < NB; n++) acc2[n] = 0ull;
        #pragma unroll
        for (int j2 = 0; j2 < KSL/2; j2++) {
            #pragma unroll
            for (int n = 0; n < NB; n++) {
                u64 h2 = *(reinterpret_cast<const u64*>(&s_h[n][g*KSL]) + j2);
                ffma2(acc2[n], h2, w2[j2], acc2[n]);
            }
        }
        #pragma unroll
        for (int n = 0; n < NB; n++) s_acc[g][n*KSL + kl] = f32x2_sum(acc2[n]);
    }
    __syncthreads();

    // combine 24 j-groups + bias + exact gelu  (NB*KSL = 256 elems)
    if (tid < NB*KSL) {
        const int idx = tid;
        float s = b1[p*KSL + (idx % KSL)];
        #pragma unroll
        for (int gg = 0; gg < JG; gg++) s += s_acc[gg][idx];
        s_h1[idx/KSL][idx%KSL] = 0.5f*s*(1.f + erff(s*0.70710678118654752f));
    }
    __syncthreads();

    // phase 2: prefetch 16 Wmu weights -> packed pairs, FFMA2 over 16 n
    {
        const float* wmp = Wmu + (size_t)(p*KSL)*QDIM + tid;
        float w[KSL];
        #pragma unroll
        for (int kk = 0; kk < KSL; kk++) w[kk] = wmp[(size_t)kk*QDIM];
        u64 w2[KSL/2];
        #pragma unroll
        for (int j2 = 0; j2 < KSL/2; j2++) w2[j2] = pack2(w[2*j2], w[2*j2+1]);

        u64 o2[NB];
        #pragma unroll
        for (int n = 0; n < NB; n++) o2[n] = 0ull;
        #pragma unroll
        for (int j2 = 0; j2 < KSL/2; j2++) {
            #pragma unroll
            for (int n = 0; n < NB; n++) {
                u64 h2 = *(reinterpret_cast<const u64*>(&s_h1[n][0]) + j2);
                ffma2(o2[n], h2, w2[j2], o2[n]);
            }
        }
        #pragma unroll
        for (int n = 0; n < NB; n++)
            g_op[(p*NB + n)*QDIM + tid] = f32x2_sum(o2[n]);
    }
}

// ---------------------------------------- kC4: final sum  (grid NB)
__global__ __launch_bounds__(QDIM)
void kC4(const float* __restrict__ bmu, float* __restrict__ out)
{
    const int n = blockIdx.x, tid = threadIdx.x;
    float s = g_pv[n*QDIM + tid] + bmu[tid];
    #pragma unroll
    for (int blk = 0; blk < 2; blk++) {
        float v[NKD/2];                   // 48 loads in flight
        #pragma unroll
        for (int p = 0; p < NKD/2; p++)
            v[p] = g_op[((blk*(NKD/2) + p)*NB + n)*QDIM + tid];
        #pragma unroll
        for (int p = 0; p < NKD/2; p++) s += v[p];
    }
    out[n*QDIM + tid] = s;
}

// ----------------------------------------------------------------- launcher
extern "C" void kernel_launch(void* const* d_in, const int* in_sizes, int n_in,
                              void* d_out, int out_size)
{
    const float* x     = (const float*)d_in[0];
    const float* Wcd   = (const float*)d_in[2];
    const float* bcd   = (const float*)d_in[3];
    const float* Wv    = (const float*)d_in[6];
    const float* bv    = (const float*)d_in[7];
    const float* lng   = (const float*)d_in[10];
    const float* lnb   = (const float*)d_in[11];
    const float* W1    = (const float*)d_in[12];
    const float* b1    = (const float*)d_in[13];
    const float* Wmu   = (const float*)d_in[14];
    const float* bmu   = (const float*)d_in[15];
    float* out = (float*)d_out;

    kB<<<dim3(CHUNKS, NB), 256>>>(x, Wcd, bcd);
    kC1b<<<dim3(8, NB), QDIM>>>(Wv);
    kC1c<<<NB, QDIM>>>(bv, lng, lnb);
    kD<<<NKD, QDIM>>>(W1, b1, Wmu);
    kC4<<<NB, QDIM>>>(bmu, out);
}

// round 14
// speedup vs baseline: 1.3718x; 1.3718x over previous
#include <cuda_runtime.h>
#include <math.h>

#define NB      16          // batch
#define MROWS   8192        // nvar * L
#define EDIM    768
#define QDIM    384
#define LSEQ    512
#define HDIM    1536
#define CHUNKS  128
#define RPC     (MROWS/CHUNKS)   // 64 rows per CTA
#define RPW     (RPC/8)          // 8 rows per warp
#define PSL     (EDIM/8)         // 96: e-slice for kC1b
#define KSL     16               // k-slice for kD
#define NKD     (HDIM/KSL)       // 96 slices
#define JG      (QDIM/KSL)       // 24 j-groups in kD phase 1

// ---- scratch (device globals; no allocs allowed) ----
__device__ float g_part[NB*CHUNKS*EDIM];// partial weighted pools (6.3 MB)
__device__ float g_wsum[NB*CHUNKS];
__device__ float g_pvp[NB*8*QDIM];      // partial pooled_v (k-split, 8 slices)
__device__ float g_h[NB*QDIM];          // LN output
__device__ float g_pv[NB*QDIM];         // pooled_v
__device__ float g_op[NKD*NB*QDIM];     // partial out (96 k-slices, 2.25 MB)

// --------------------------------------------------------- f32x2 packed math
typedef unsigned long long u64;

__device__ __forceinline__ void ffma2(u64 &d, u64 a, u64 b, u64 c) {
    asm("fma.rn.f32x2 %0, %1, %2, %3;" : "=l"(d) : "l"(a), "l"(b), "l"(c));
}
__device__ __forceinline__ float f32x2_sum(u64 v) {
    float lo, hi;
    asm("mov.b64 {%0, %1}, %2;" : "=f"(lo), "=f"(hi) : "l"(v));
    return lo + hi;
}
__device__ __forceinline__ u64 pack2(float lo, float hi) {
    u64 r;
    asm("mov.b64 %0, {%1, %2};" : "=l"(r) : "f"(lo), "f"(hi));
    return r;
}

// ---------------------------------------------------------------- reductions
__device__ __forceinline__ float blockReduce384(float v, float* s_red, int tid) {
    s_red[tid] = v; __syncthreads();
    if (tid < 128) s_red[tid] += s_red[tid + 128] + s_red[tid + 256];
    __syncthreads();
    #pragma unroll
    for (int o = 64; o > 0; o >>= 1) {
        if (tid < o) s_red[tid] += s_red[tid + o];
        __syncthreads();
    }
    float r = s_red[0]; __syncthreads();
    return r;
}

__device__ __forceinline__ float warpSum(float v) {
    #pragma unroll
    for (int o = 16; o > 0; o >>= 1) v += __shfl_xor_sync(0xffffffffu, v, o);
    return v;
}

// --------------------- kernel B: fused x-stream (FFMA2 packed) ---------------
// retrieval logit = 0.5*imp + 0.2*rec  (relevance is constant to ~2e-5 and
// cancels in the softmax; the whole query/Wk path is dead)
__global__ __launch_bounds__(256, 2)
void kB(const float* __restrict__ x, const float* __restrict__ Wcd,
        const float* __restrict__ bcd)
{
    __shared__ float s_c0[EDIM], s_c1[EDIM];
    __shared__ float s_rec[LSEQ];
    __shared__ float s_part[8][EDIM];
    __shared__ float s_ws[8];

    const int n = blockIdx.y, chunk = blockIdx.x;
    const int tid = threadIdx.x, lane = tid & 31, warp = tid >> 5;

    for (int e = tid; e < EDIM; e += 256) {
        s_c0[e] = Wcd[2*e];
        s_c1[e] = Wcd[2*e + 1];
    }
    for (int p = tid; p < LSEQ; p += 256)
        s_rec[p] = 0.2f * __expf(-0.00300450902029873f * (float)(511 - p));
    __syncthreads();

    const float b0 = bcd[0], b1v = bcd[1];

    const ulonglong2* c02 = reinterpret_cast<const ulonglong2*>(s_c0);
    const ulonglong2* c12 = reinterpret_cast<const ulonglong2*>(s_c1);

    u64 acc2[12];
    #pragma unroll
    for (int i = 0; i < 12; i++) acc2[i] = 0ull;
    float wsum = 0.f;

    const int row0 = chunk*RPC + warp*RPW;
    const ulonglong2* xb = reinterpret_cast<const ulonglong2*>(x)
                         + (size_t)n * MROWS * (EDIM/4) + lane;

    for (int r = 0; r < RPW; r += 2) {
        const int m = row0 + r;
        const ulonglong2* xra = xb + (size_t)m * (EDIM/4);
        const ulonglong2* xrb = xra + (EDIM/4);
        ulonglong2 va2[6], vb2[6];
        #pragma unroll
        for (int i = 0; i < 6; i++) va2[i] = xra[32*i];
        #pragma unroll
        for (int i = 0; i < 6; i++) vb2[i] = xrb[32*i];

        u64 d0a2 = 0, d1a2 = 0, d0b2 = 0, d1b2 = 0;
        #pragma unroll
        for (int i = 0; i < 6; i++) {
            const int idx = lane + 32*i;
            ulonglong2 w0 = c02[idx];       // one LDS.128 for both rows
            ffma2(d0a2, va2[i].x, w0.x, d0a2);
            ffma2(d0a2, va2[i].y, w0.y, d0a2);
            ffma2(d0b2, vb2[i].x, w0.x, d0b2);
            ffma2(d0b2, vb2[i].y, w0.y, d0b2);
            ulonglong2 w1 = c12[idx];
            ffma2(d1a2, va2[i].x, w1.x, d1a2);
            ffma2(d1a2, va2[i].y, w1.y, d1a2);
            ffma2(d1b2, vb2[i].x, w1.x, d1b2);
            ffma2(d1b2, vb2[i].y, w1.y, d1b2);
        }
        float d0a = f32x2_sum(d0a2), d1a = f32x2_sum(d1a2);
        float d0b = f32x2_sum(d0b2), d1b = f32x2_sum(d1b2);

        #pragma unroll
        for (int o = 16; o > 0; o >>= 1) {
            d0a += __shfl_xor_sync(0xffffffffu, d0a, o);
            d0b += __shfl_xor_sync(0xffffffffu, d0b, o);
            d1a += __shfl_xor_sync(0xffffffffu, d1a, o);
            d1b += __shfl_xor_sync(0xffffffffu, d1b, o);
        }

        // importance: imp = 1/(1+(A1/A0)^2), A = 1+e^z, z = -(cd + b)
        float A0a = 1.f + __expf(-(d0a + b0));
        float A1a = 1.f + __expf(-(d1a + b1v));
        float A0b = 1.f + __expf(-(d0b + b0));
        float A1b = 1.f + __expf(-(d1b + b1v));
        float ra  = __fdividef(A1a, A0a);
        float rb  = __fdividef(A1b, A0b);
        float impa = __fdividef(1.f, fmaf(ra, ra, 1.f));
        float impb = __fdividef(1.f, fmaf(rb, rb, 1.f));

        float reca = s_rec[ m      & (LSEQ-1)];
        float recb = s_rec[(m + 1) & (LSEQ-1)];

        float wA = __expf(0.5f*impa + reca);
        float wB = __expf(0.5f*impb + recb);
        wsum += wA + wB;

        u64 wA2 = pack2(wA, wA), wB2 = pack2(wB, wB);
        #pragma unroll
        for (int i = 0; i < 6; i++) {
            ffma2(acc2[2*i],   va2[i].x, wA2, acc2[2*i]);
            ffma2(acc2[2*i],   vb2[i].x, wB2, acc2[2*i]);
            ffma2(acc2[2*i+1], va2[i].y, wA2, acc2[2*i+1]);
            ffma2(acc2[2*i+1], vb2[i].y, wB2, acc2[2*i+1]);
        }
    }

    // warp partials -> smem, fixed-order CTA reduce
    ulonglong2* sp2 = reinterpret_cast<ulonglong2*>(s_part[warp]);
    #pragma unroll
    for (int i = 0; i < 6; i++)
        sp2[lane + 32*i] = make_ulonglong2(acc2[2*i], acc2[2*i+1]);
    if (lane == 0) s_ws[warp] = wsum;
    __syncthreads();

    float* gp = g_part + (size_t)(n*CHUNKS + chunk)*EDIM;
    for (int e = tid; e < EDIM; e += 256) {
        float s = 0.f;
        #pragma unroll
        for (int wi = 0; wi < 8; wi++) s += s_part[wi][e];
        gp[e] = s;
    }
    if (tid == 0) {
        float s = 0.f;
        #pragma unroll
        for (int wi = 0; wi < 8; wi++) s += s_ws[wi];
        g_wsum[n*CHUNKS + chunk] = s;
    }
}

// ----------- kC1b: reduce partial pools (own e-slice) + partial Wv matvec
//             grid (8, NB), 384 threads; 4 threads/element over 128 chunks
__global__ __launch_bounds__(QDIM)
void kC1b(const float* __restrict__ Wv)
{
    __shared__ float s_q[4][PSL];
    __shared__ float s_px[PSL];
    const int p = blockIdx.x, n = blockIdx.y, tid = threadIdx.x;
    const int ebase = p*PSL;
    const int el = tid % PSL, grp = tid / PSL;    // 4 threads per element

    {
        const float* pp = g_part + (size_t)n*CHUNKS*EDIM
                        + (size_t)(grp*(CHUNKS/4))*EDIM + ebase + el;
        float v[CHUNKS/4];                        // 32 loads in flight
        #pragma unroll
        for (int c = 0; c < CHUNKS/4; c++) v[c] = pp[(size_t)c*EDIM];
        float s = 0.f;
        #pragma unroll
        for (int c = 0; c < CHUNKS/4; c++) s += v[c];
        s_q[grp][el] = s;
    }
    __syncthreads();
    if (tid < PSL)
        s_px[tid] = (s_q[0][tid] + s_q[1][tid]) + (s_q[2][tid] + s_q[3][tid]);
    __syncthreads();

    // Wv matvec: 3 blocks of 32 register-prefetched weight loads
    float s = 0.f;
    const float* wv = Wv + (size_t)ebase*QDIM + tid;
    #pragma unroll
    for (int blk = 0; blk < 3; blk++) {
        float w[32];
        #pragma unroll
        for (int i = 0; i < 32; i++) w[i] = wv[(size_t)(blk*32 + i)*QDIM];
        #pragma unroll
        for (int i = 0; i < 32; i++) s += s_px[blk*32 + i]*w[i];
    }
    g_pvp[(n*8 + p)*QDIM + tid] = s;
}

// ----------- kC1c: wsum, combine partials, + bv, LayerNorm  (grid NB, 384)
__global__ __launch_bounds__(QDIM)
void kC1c(const float* __restrict__ bv, const float* __restrict__ lng,
          const float* __restrict__ lnb)
{
    __shared__ float s_red[QDIM];
    __shared__ float s_inv;
    const int n = blockIdx.x, tid = threadIdx.x;

    if (tid < 32) {
        float s = 0.f;
        #pragma unroll
        for (int q = 0; q < CHUNKS/32; q++) s += g_wsum[n*CHUNKS + tid + 32*q];
        s = warpSum(s);
        if (tid == 0) s_inv = 1.f/s;
    }
    __syncthreads();
    const float inv = s_inv;

    float s = 0.f;
    #pragma unroll
    for (int p = 0; p < 8; p++) s += g_pvp[(n*8 + p)*QDIM + tid];
    s = s*inv + bv[tid];

    float mean = blockReduce384(s, s_red, tid) * (1.f/(float)QDIM);
    float d    = s - mean;
    float var  = blockReduce384(d*d, s_red, tid) * (1.f/(float)QDIM);
    g_h[n*QDIM + tid]  = lng[tid]*d*rsqrtf(var + 1e-6f) + lnb[tid];
    g_pv[n*QDIM + tid] = s;
}

// ------------- kD: batched FFN. grid NKD=96, 384 thr, k-slice of 16.
// Register-prefetched weights + FFMA2/LDS.64 packed inner products.
__global__ __launch_bounds__(QDIM)
void kD(const float* __restrict__ W1, const float* __restrict__ b1,
        const float* __restrict__ Wmu)
{
    __shared__ float s_h[NB][QDIM];      // 24 KB
    __shared__ float s_acc[JG][NB*KSL];  // 24*256*4 = 24 KB
    __shared__ float s_h1[NB][KSL];      // 1 KB
    const int p = blockIdx.x, tid = threadIdx.x;
    const int kl = tid % KSL, g = tid / KSL;   // 16 k-lanes x 24 j-groups
    const int k = p*KSL + kl;

    // cooperative h load, float4 (4 iters)
    {
        const float4* gh4 = reinterpret_cast<const float4*>(g_h);
        float4* sh4 = reinterpret_cast<float4*>(&s_h[0][0]);
        #pragma unroll
        for (int q = 0; q < NB*QDIM/4/QDIM; q++)
            sh4[tid + q*QDIM] = gh4[tid + q*QDIM];
    }
    __syncthreads();

    // phase 1: prefetch 16 W1 weights -> 8 packed pairs, then FFMA2
    {
        const float* w1p = W1 + (size_t)(g*KSL)*HDIM + k;
        float w[KSL];
        #pragma unroll
        for (int j = 0; j < KSL; j++) w[j] = w1p[(size_t)j*HDIM];
        u64 w2[KSL/2];
        #pragma unroll
        for (int j2 = 0; j2 < KSL/2; j2++) w2[j2] = pack2(w[2*j2], w[2*j2+1]);

        u64 acc2[NB];
        #pragma unroll
        for (int n = 0; n < NB; n++) acc2[n] = 0ull;
        #pragma unroll
        for (int j2 = 0; j2 < KSL/2; j2++) {
            #pragma unroll
            for (int n = 0; n < NB; n++) {
                u64 h2 = *(reinterpret_cast<const u64*>(&s_h[n][g*KSL]) + j2);
                ffma2(acc2[n], h2, w2[j2], acc2[n]);
            }
        }
        #pragma unroll
        for (int n = 0; n < NB; n++) s_acc[g][n*KSL + kl] = f32x2_sum(acc2[n]);
    }
    __syncthreads();

    // combine 24 j-groups + bias + exact gelu  (NB*KSL = 256 elems)
    if (tid < NB*KSL) {
        const int idx = tid;
        float s = b1[p*KSL + (idx % KSL)];
        #pragma unroll
        for (int gg = 0; gg < JG; gg++) s += s_acc[gg][idx];
        s_h1[idx/KSL][idx%KSL] = 0.5f*s*(1.f + erff(s*0.70710678118654752f));
    }
    __syncthreads();

    // phase 2: prefetch 16 Wmu weights -> packed pairs, FFMA2 over 16 n
    {
        const float* wmp = Wmu + (size_t)(p*KSL)*QDIM + tid;
        float w[KSL];
        #pragma unroll
        for (int kk = 0; kk < KSL; kk++) w[kk] = wmp[(size_t)kk*QDIM];
        u64 w2[KSL/2];
        #pragma unroll
        for (int j2 = 0; j2 < KSL/2; j2++) w2[j2] = pack2(w[2*j2], w[2*j2+1]);

        u64 o2[NB];
        #pragma unroll
        for (int n = 0; n < NB; n++) o2[n] = 0ull;
        #pragma unroll
        for (int j2 = 0; j2 < KSL/2; j2++) {
            #pragma unroll
            for (int n = 0; n < NB; n++) {
                u64 h2 = *(reinterpret_cast<const u64*>(&s_h1[n][0]) + j2);
                ffma2(o2[n], h2, w2[j2], o2[n]);
            }
        }
        #pragma unroll
        for (int n = 0; n < NB; n++)
            g_op[(p*NB + n)*QDIM + tid] = f32x2_sum(o2[n]);
    }
}

// ---------------------------------------- kC4: final sum  (grid NB)
__global__ __launch_bounds__(QDIM)
void kC4(const float* __restrict__ bmu, float* __restrict__ out)
{
    const int n = blockIdx.x, tid = threadIdx.x;
    float s = g_pv[n*QDIM + tid] + bmu[tid];
    #pragma unroll
    for (int blk = 0; blk < 2; blk++) {
        float v[NKD/2];                   // 48 loads in flight
        #pragma unroll
        for (int p = 0; p < NKD/2; p++)
            v[p] = g_op[((blk*(NKD/2) + p)*NB + n)*QDIM + tid];
        #pragma unroll
        for (int p = 0; p < NKD/2; p++) s += v[p];
    }
    out[n*QDIM + tid] = s;
}

// ----------------------------------------------------------------- launcher
extern "C" void kernel_launch(void* const* d_in, const int* in_sizes, int n_in,
                              void* d_out, int out_size)
{
    const float* x     = (const float*)d_in[0];
    const float* Wcd   = (const float*)d_in[2];
    const float* bcd   = (const float*)d_in[3];
    const float* Wv    = (const float*)d_in[6];
    const float* bv    = (const float*)d_in[7];
    const float* lng   = (const float*)d_in[10];
    const float* lnb   = (const float*)d_in[11];
    const float* W1    = (const float*)d_in[12];
    const float* b1    = (const float*)d_in[13];
    const float* Wmu   = (const float*)d_in[14];
    const float* bmu   = (const float*)d_in[15];
    float* out = (float*)d_out;

    kB<<<dim3(CHUNKS, NB), 256>>>(x, Wcd, bcd);
    kC1b<<<dim3(8, NB), QDIM>>>(Wv);
    kC1c<<<NB, QDIM>>>(bv, lng, lnb);
    kD<<<NKD, QDIM>>>(W1, b1, Wmu);
    kC4<<<NB, QDIM>>>(bmu, out);
}

// round 15
// speedup vs baseline: 1.6442x; 1.1986x over previous
#include <cuda_runtime.h>
#include <math.h>

#define NB      16          // batch
#define MROWS   8192        // nvar * L
#define EDIM    768
#define QDIM    384
#define LSEQ    512
#define HDIM    1536
#define CHUNKS  128
#define RPC     (MROWS/CHUNKS)   // 64 rows per CTA
#define RPW     (RPC/8)          // 8 rows per warp
#define PSL     (EDIM/8)         // 96: e-slice for kC1b
#define KSL     16               // k-slice for kD
#define NKD     (HDIM/KSL)       // 96 slices
#define JG      (QDIM/KSL)       // 24 j-groups in kD phase 1

// ---- scratch (device globals; no allocs allowed) ----
__device__ float g_part[NB*CHUNKS*EDIM];// partial weighted pools (6.3 MB)
__device__ float g_wsum[NB*CHUNKS];
__device__ float g_pvp[NB*8*QDIM];      // partial pooled_v (k-split, 8 slices)
__device__ float g_h[NB*QDIM];          // LN output
__device__ float g_pv[NB*QDIM];         // pooled_v
__device__ float g_op[NKD*NB*QDIM];     // partial out (96 k-slices, 2.25 MB)

// --------------------------------------------------------- f32x2 packed math
typedef unsigned long long u64;

__device__ __forceinline__ void ffma2(u64 &d, u64 a, u64 b, u64 c) {
    asm("fma.rn.f32x2 %0, %1, %2, %3;" : "=l"(d) : "l"(a), "l"(b), "l"(c));
}
__device__ __forceinline__ float f32x2_sum(u64 v) {
    float lo, hi;
    asm("mov.b64 {%0, %1}, %2;" : "=f"(lo), "=f"(hi) : "l"(v));
    return lo + hi;
}
__device__ __forceinline__ u64 pack2(float lo, float hi) {
    u64 r;
    asm("mov.b64 %0, {%1, %2};" : "=l"(r) : "f"(lo), "f"(hi));
    return r;
}
// streaming 16B load (evict-first) -> packed pair form
__device__ __forceinline__ void ldcs2(const float4* p, u64 &lo, u64 &hi) {
    float4 t = __ldcs(p);
    lo = pack2(t.x, t.y);
    hi = pack2(t.z, t.w);
}

// ---------------------------------------------------------------- reductions
__device__ __forceinline__ float blockReduce384(float v, float* s_red, int tid) {
    s_red[tid] = v; __syncthreads();
    if (tid < 128) s_red[tid] += s_red[tid + 128] + s_red[tid + 256];
    __syncthreads();
    #pragma unroll
    for (int o = 64; o > 0; o >>= 1) {
        if (tid < o) s_red[tid] += s_red[tid + o];
        __syncthreads();
    }
    float r = s_red[0]; __syncthreads();
    return r;
}

__device__ __forceinline__ float warpSum(float v) {
    #pragma unroll
    for (int o = 16; o > 0; o >>= 1) v += __shfl_xor_sync(0xffffffffu, v, o);
    return v;
}

// --------------------- kernel B: fused x-stream (FFMA2 packed) ---------------
// retrieval logit = 0.5*imp + 0.2*rec  (relevance is constant to ~2e-5 and
// cancels in the softmax; the whole query/Wk path is dead)
__global__ __launch_bounds__(256, 2)
void kB(const float* __restrict__ x, const float* __restrict__ Wcd,
        const float* __restrict__ bcd)
{
    __shared__ float s_c0[EDIM], s_c1[EDIM];
    __shared__ float s_rec[LSEQ];
    __shared__ float s_part[8][EDIM];
    __shared__ float s_ws[8];

    const int n = blockIdx.y, chunk = blockIdx.x;
    const int tid = threadIdx.x, lane = tid & 31, warp = tid >> 5;

    for (int e = tid; e < EDIM; e += 256) {
        s_c0[e] = Wcd[2*e];
        s_c1[e] = Wcd[2*e + 1];
    }
    for (int p = tid; p < LSEQ; p += 256)
        s_rec[p] = 0.2f * __expf(-0.00300450902029873f * (float)(511 - p));
    __syncthreads();

    const float b0 = bcd[0], b1v = bcd[1];

    const ulonglong2* c02 = reinterpret_cast<const ulonglong2*>(s_c0);
    const ulonglong2* c12 = reinterpret_cast<const ulonglong2*>(s_c1);

    u64 acc2[12];
    #pragma unroll
    for (int i = 0; i < 12; i++) acc2[i] = 0ull;
    float wsum = 0.f;

    const int row0 = chunk*RPC + warp*RPW;
    const float4* xb = reinterpret_cast<const float4*>(x)
                     + (size_t)n * MROWS * (EDIM/4) + lane;

    for (int r = 0; r < RPW; r += 2) {
        const int m = row0 + r;
        const float4* xra = xb + (size_t)m * (EDIM/4);
        const float4* xrb = xra + (EDIM/4);
        u64 va2[12], vb2[12];
        #pragma unroll
        for (int i = 0; i < 6; i++) ldcs2(xra + 32*i, va2[2*i], va2[2*i+1]);
        #pragma unroll
        for (int i = 0; i < 6; i++) ldcs2(xrb + 32*i, vb2[2*i], vb2[2*i+1]);

        u64 d0a2 = 0, d1a2 = 0, d0b2 = 0, d1b2 = 0;
        #pragma unroll
        for (int i = 0; i < 6; i++) {
            const int idx = lane + 32*i;
            ulonglong2 w0 = c02[idx];       // one LDS.128 for both rows
            ffma2(d0a2, va2[2*i],   w0.x, d0a2);
            ffma2(d0a2, va2[2*i+1], w0.y, d0a2);
            ffma2(d0b2, vb2[2*i],   w0.x, d0b2);
            ffma2(d0b2, vb2[2*i+1], w0.y, d0b2);
            ulonglong2 w1 = c12[idx];
            ffma2(d1a2, va2[2*i],   w1.x, d1a2);
            ffma2(d1a2, va2[2*i+1], w1.y, d1a2);
            ffma2(d1b2, vb2[2*i],   w1.x, d1b2);
            ffma2(d1b2, vb2[2*i+1], w1.y, d1b2);
        }
        float d0a = f32x2_sum(d0a2), d1a = f32x2_sum(d1a2);
        float d0b = f32x2_sum(d0b2), d1b = f32x2_sum(d1b2);

        #pragma unroll
        for (int o = 16; o > 0; o >>= 1) {
            d0a += __shfl_xor_sync(0xffffffffu, d0a, o);
            d0b += __shfl_xor_sync(0xffffffffu, d0b, o);
            d1a += __shfl_xor_sync(0xffffffffu, d1a, o);
            d1b += __shfl_xor_sync(0xffffffffu, d1b, o);
        }

        // importance: imp = 1/(1+(A1/A0)^2), A = 1+e^z, z = -(cd + b)
        float A0a = 1.f + __expf(-(d0a + b0));
        float A1a = 1.f + __expf(-(d1a + b1v));
        float A0b = 1.f + __expf(-(d0b + b0));
        float A1b = 1.f + __expf(-(d1b + b1v));
        float ra  = __fdividef(A1a, A0a);
        float rb  = __fdividef(A1b, A0b);
        float impa = __fdividef(1.f, fmaf(ra, ra, 1.f));
        float impb = __fdividef(1.f, fmaf(rb, rb, 1.f));

        float reca = s_rec[ m      & (LSEQ-1)];
        float recb = s_rec[(m + 1) & (LSEQ-1)];

        float wA = __expf(0.5f*impa + reca);
        float wB = __expf(0.5f*impb + recb);
        wsum += wA + wB;

        u64 wA2 = pack2(wA, wA), wB2 = pack2(wB, wB);
        #pragma unroll
        for (int i = 0; i < 12; i++) {
            ffma2(acc2[i], va2[i], wA2, acc2[i]);
            ffma2(acc2[i], vb2[i], wB2, acc2[i]);
        }
    }

    // warp partials -> smem, fixed-order CTA reduce
    ulonglong2* sp2 = reinterpret_cast<ulonglong2*>(s_part[warp]);
    #pragma unroll
    for (int i = 0; i < 6; i++)
        sp2[lane + 32*i] = make_ulonglong2(acc2[2*i], acc2[2*i+1]);
    if (lane == 0) s_ws[warp] = wsum;
    __syncthreads();

    float* gp = g_part + (size_t)(n*CHUNKS + chunk)*EDIM;
    for (int e = tid; e < EDIM; e += 256) {
        float s = 0.f;
        #pragma unroll
        for (int wi = 0; wi < 8; wi++) s += s_part[wi][e];
        __stcs(gp + e, s);
    }
    if (tid == 0) {
        float s = 0.f;
        #pragma unroll
        for (int wi = 0; wi < 8; wi++) s += s_ws[wi];
        g_wsum[n*CHUNKS + chunk] = s;
    }
}

// ----------- kC1b: reduce partial pools (own e-slice) + partial Wv matvec
//             grid (8, NB), 384 threads; 4 threads/element over 128 chunks
__global__ __launch_bounds__(QDIM)
void kC1b(const float* __restrict__ Wv)
{
    __shared__ float s_q[4][PSL];
    __shared__ float s_px[PSL];
    const int p = blockIdx.x, n = blockIdx.y, tid = threadIdx.x;
    const int ebase = p*PSL;
    const int el = tid % PSL, grp = tid / PSL;    // 4 threads per element

    {
        const float* pp = g_part + (size_t)n*CHUNKS*EDIM
                        + (size_t)(grp*(CHUNKS/4))*EDIM + ebase + el;
        float v[CHUNKS/4];                        // 32 loads in flight
        #pragma unroll
        for (int c = 0; c < CHUNKS/4; c++) v[c] = __ldcs(pp + (size_t)c*EDIM);
        float s = 0.f;
        #pragma unroll
        for (int c = 0; c < CHUNKS/4; c++) s += v[c];
        s_q[grp][el] = s;
    }
    __syncthreads();
    if (tid < PSL)
        s_px[tid] = (s_q[0][tid] + s_q[1][tid]) + (s_q[2][tid] + s_q[3][tid]);
    __syncthreads();

    // Wv matvec: 3 blocks of 32 register-prefetched weight loads
    float s = 0.f;
    const float* wv = Wv + (size_t)ebase*QDIM + tid;
    #pragma unroll
    for (int blk = 0; blk < 3; blk++) {
        float w[32];
        #pragma unroll
        for (int i = 0; i < 32; i++) w[i] = wv[(size_t)(blk*32 + i)*QDIM];
        #pragma unroll
        for (int i = 0; i < 32; i++) s += s_px[blk*32 + i]*w[i];
    }
    g_pvp[(n*8 + p)*QDIM + tid] = s;
}

// ----------- kC1c: wsum, combine partials, + bv, LayerNorm  (grid NB, 384)
__global__ __launch_bounds__(QDIM)
void kC1c(const float* __restrict__ bv, const float* __restrict__ lng,
          const float* __restrict__ lnb)
{
    __shared__ float s_red[QDIM];
    __shared__ float s_inv;
    const int n = blockIdx.x, tid = threadIdx.x;

    if (tid < 32) {
        float s = 0.f;
        #pragma unroll
        for (int q = 0; q < CHUNKS/32; q++) s += g_wsum[n*CHUNKS + tid + 32*q];
        s = warpSum(s);
        if (tid == 0) s_inv = 1.f/s;
    }
    __syncthreads();
    const float inv = s_inv;

    float s = 0.f;
    #pragma unroll
    for (int p = 0; p < 8; p++) s += g_pvp[(n*8 + p)*QDIM + tid];
    s = s*inv + bv[tid];

    float mean = blockReduce384(s, s_red, tid) * (1.f/(float)QDIM);
    float d    = s - mean;
    float var  = blockReduce384(d*d, s_red, tid) * (1.f/(float)QDIM);
    g_h[n*QDIM + tid]  = lng[tid]*d*rsqrtf(var + 1e-6f) + lnb[tid];
    g_pv[n*QDIM + tid] = s;
}

// ------------- kD: batched FFN. grid NKD=96, 384 thr, k-slice of 16.
// ALL weight prefetches (W1 phase-1 AND Wmu phase-2) issued up front so both
// DRAM latency waves overlap with the h load; FFMA2 packed inner products.
__global__ __launch_bounds__(QDIM)
void kD(const float* __restrict__ W1, const float* __restrict__ b1,
        const float* __restrict__ Wmu)
{
    __shared__ float s_h[NB][QDIM];      // 24 KB
    __shared__ float s_acc[JG][NB*KSL];  // 24 KB
    __shared__ float s_h1[NB][KSL];      // 1 KB
    const int p = blockIdx.x, tid = threadIdx.x;
    const int kl = tid % KSL, g = tid / KSL;   // 16 k-lanes x 24 j-groups
    const int k = p*KSL + kl;

    // ---- issue ALL independent loads first (one latency wave) ----
    // phase-1 weights
    const float* w1p = W1 + (size_t)(g*KSL)*HDIM + k;
    float w[KSL];
    #pragma unroll
    for (int j = 0; j < KSL; j++) w[j] = w1p[(size_t)j*HDIM];
    // phase-2 weights (independent of everything before phase 2)
    const float* wmp = Wmu + (size_t)(p*KSL)*QDIM + tid;
    float wm[KSL];
    #pragma unroll
    for (int kk = 0; kk < KSL; kk++) wm[kk] = wmp[(size_t)kk*QDIM];
    // cooperative h load, float4 (4 iters)
    {
        const float4* gh4 = reinterpret_cast<const float4*>(g_h);
        float4* sh4 = reinterpret_cast<float4*>(&s_h[0][0]);
        #pragma unroll
        for (int q = 0; q < NB*QDIM/4/QDIM; q++)
            sh4[tid + q*QDIM] = gh4[tid + q*QDIM];
    }
    __syncthreads();

    // phase 1: packed pairs + FFMA2
    {
        u64 w2[KSL/2];
        #pragma unroll
        for (int j2 = 0; j2 < KSL/2; j2++) w2[j2] = pack2(w[2*j2], w[2*j2+1]);

        u64 acc2[NB];
        #pragma unroll
        for (int n = 0; n < NB; n++) acc2[n] = 0ull;
        #pragma unroll
        for (int j2 = 0; j2 < KSL/2; j2++) {
            #pragma unroll
            for (int n = 0; n < NB; n++) {
                u64 h2 = *(reinterpret_cast<const u64*>(&s_h[n][g*KSL]) + j2);
                ffma2(acc2[n], h2, w2[j2], acc2[n]);
            }
        }
        #pragma unroll
        for (int n = 0; n < NB; n++) s_acc[g][n*KSL + kl] = f32x2_sum(acc2[n]);
    }
    __syncthreads();

    // combine 24 j-groups + bias + exact gelu  (NB*KSL = 256 elems)
    if (tid < NB*KSL) {
        const int idx = tid;
        float s = b1[p*KSL + (idx % KSL)];
        #pragma unroll
        for (int gg = 0; gg < JG; gg++) s += s_acc[gg][idx];
        s_h1[idx/KSL][idx%KSL] = 0.5f*s*(1.f + erff(s*0.70710678118654752f));
    }
    __syncthreads();

    // phase 2: weights already resident in registers
    {
        u64 w2[KSL/2];
        #pragma unroll
        for (int j2 = 0; j2 < KSL/2; j2++) w2[j2] = pack2(wm[2*j2], wm[2*j2+1]);

        u64 o2[NB];
        #pragma unroll
        for (int n = 0; n < NB; n++) o2[n] = 0ull;
        #pragma unroll
        for (int j2 = 0; j2 < KSL/2; j2++) {
            #pragma unroll
            for (int n = 0; n < NB; n++) {
                u64 h2 = *(reinterpret_cast<const u64*>(&s_h1[n][0]) + j2);
                ffma2(o2[n], h2, w2[j2], o2[n]);
            }
        }
        #pragma unroll
        for (int n = 0; n < NB; n++)
            g_op[(p*NB + n)*QDIM + tid] = f32x2_sum(o2[n]);
    }
}

// ---------------------------------------- kC4: final sum  (grid NB)
__global__ __launch_bounds__(QDIM)
void kC4(const float* __restrict__ bmu, float* __restrict__ out)
{
    const int n = blockIdx.x, tid = threadIdx.x;
    float s = g_pv[n*QDIM + tid] + bmu[tid];
    #pragma unroll
    for (int blk = 0; blk < 2; blk++) {
        float v[NKD/2];                   // 48 loads in flight
        #pragma unroll
        for (int p = 0; p < NKD/2; p++)
            v[p] = g_op[((blk*(NKD/2) + p)*NB + n)*QDIM + tid];
        #pragma unroll
        for (int p = 0; p < NKD/2; p++) s += v[p];
    }
    out[n*QDIM + tid] = s;
}

// ----------------------------------------------------------------- launcher
extern "C" void kernel_launch(void* const* d_in, const int* in_sizes, int n_in,
                              void* d_out, int out_size)
{
    const float* x     = (const float*)d_in[0];
    const float* Wcd   = (const float*)d_in[2];
    const float* bcd   = (const float*)d_in[3];
    const float* Wv    = (const float*)d_in[6];
    const float* bv    = (const float*)d_in[7];
    const float* lng   = (const float*)d_in[10];
    const float* lnb   = (const float*)d_in[11];
    const float* W1    = (const float*)d_in[12];
    const float* b1    = (const float*)d_in[13];
    const float* Wmu   = (const float*)d_in[14];
    const float* bmu   = (const float*)d_in[15];
    float* out = (float*)d_out;

    kB<<<dim3(CHUNKS, NB), 256>>>(x, Wcd, bcd);
    kC1b<<<dim3(8, NB), QDIM>>>(Wv);
    kC1c<<<NB, QDIM>>>(bv, lng, lnb);
    kD<<<NKD, QDIM>>>(W1, b1, Wmu);
    kC4<<<NB, QDIM>>>(bmu, out);
}